// round 8
// baseline (speedup 1.0000x reference)
#include <cuda_runtime.h>
#include <cstdint>
#include <cstddef>

#define NB    64      // batch
#define NS    512     // seq len
#define NE    512     // embed dim
#define NH    1024    // hidden
#define NG    4096    // 4*H
#define NCTA  128     // persistent CTAs (1 per SM, <=148)

// ---------------- scratch (device globals: sanctioned, no allocation) ----------------
__device__ float g_xproj[(size_t)NS * NB * NG];   // 512 MB: [s][b][4H]
__device__ float g_hbuf[2][NB * NH];              // double-buffered h
__device__ unsigned int g_bar_arrive;
__device__ unsigned int g_bar_gen;

__global__ void init_kernel() {
    g_bar_arrive = 0u;
    g_bar_gen = 0u;
}

__device__ __forceinline__ float sigm(float v) { return 1.0f / (1.0f + __expf(-v)); }

// =====================================================================
// Kernel A: xproj[s][b][g] = sum_e emb[x[b][s]][e] * W_ih[g][e] + b_ih[g]
// GEMM M=32768 (m = s*64+b), N=4096, K=512. BM=BN=128, BK=16, 256 thr, 8x8/thread.
// =====================================================================
__global__ __launch_bounds__(256, 2)
void xproj_kernel(const int* __restrict__ x,
                  const float* __restrict__ emb,
                  const float* __restrict__ W_ih,
                  const float* __restrict__ b_ih)
{
    __shared__ float As[16][132];   // transposed tiles, padded stride
    __shared__ float Bs[16][132];

    const int tid = threadIdx.x;
    const int nt = blockIdx.x;       // 0..31
    const int mt = blockIdx.y;       // 0..255
    const int m0 = mt * 128;
    const int n0 = nt * 128;

    const int lrow = tid >> 2;       // 0..63
    const int lch  = tid & 3;        // float4 chunk within 16-k slab

    // A source rows (gathered embedding rows); tokens hoisted out of k loop
    const int mA0 = m0 + lrow;
    const int mA1 = mA0 + 64;
    const int tok0 = x[(mA0 & 63) * NS + (mA0 >> 6)];
    const int tok1 = x[(mA1 & 63) * NS + (mA1 >> 6)];
    const float4* a0p = (const float4*)(emb + (size_t)tok0 * NE);
    const float4* a1p = (const float4*)(emb + (size_t)tok1 * NE);
    const float4* b0p = (const float4*)(W_ih + (size_t)(n0 + lrow) * NE);
    const float4* b1p = (const float4*)(W_ih + (size_t)(n0 + lrow + 64) * NE);

    const int tx = tid & 15;         // n-dir thread coord
    const int ty = tid >> 4;         // m-dir thread coord

    float acc[8][8];
#pragma unroll
    for (int i = 0; i < 8; i++)
#pragma unroll
        for (int j = 0; j < 8; j++) acc[i][j] = 0.0f;

    // prefetch first slab
    float4 av0 = a0p[lch], av1 = a1p[lch], bv0 = b0p[lch], bv1 = b1p[lch];

    for (int kt = 0; kt < 32; kt++) {
        const int kl = lch * 4;
        As[kl + 0][lrow]      = av0.x; As[kl + 1][lrow]      = av0.y;
        As[kl + 2][lrow]      = av0.z; As[kl + 3][lrow]      = av0.w;
        As[kl + 0][lrow + 64] = av1.x; As[kl + 1][lrow + 64] = av1.y;
        As[kl + 2][lrow + 64] = av1.z; As[kl + 3][lrow + 64] = av1.w;
        Bs[kl + 0][lrow]      = bv0.x; Bs[kl + 1][lrow]      = bv0.y;
        Bs[kl + 2][lrow]      = bv0.z; Bs[kl + 3][lrow]      = bv0.w;
        Bs[kl + 0][lrow + 64] = bv1.x; Bs[kl + 1][lrow + 64] = bv1.y;
        Bs[kl + 2][lrow + 64] = bv1.z; Bs[kl + 3][lrow + 64] = bv1.w;
        __syncthreads();

        if (kt < 31) {   // prefetch next slab to hide L2 latency behind compute
            const int kc = (kt + 1) * 4 + lch;
            av0 = a0p[kc]; av1 = a1p[kc]; bv0 = b0p[kc]; bv1 = b1p[kc];
        }

#pragma unroll
        for (int k = 0; k < 16; k++) {
            const float4 aa0 = *(const float4*)&As[k][ty * 8];
            const float4 aa1 = *(const float4*)&As[k][ty * 8 + 4];
            const float4 ba0 = *(const float4*)&Bs[k][tx * 8];
            const float4 ba1 = *(const float4*)&Bs[k][tx * 8 + 4];
            const float a[8] = {aa0.x, aa0.y, aa0.z, aa0.w, aa1.x, aa1.y, aa1.z, aa1.w};
            const float bq[8] = {ba0.x, ba0.y, ba0.z, ba0.w, ba1.x, ba1.y, ba1.z, ba1.w};
#pragma unroll
            for (int i = 0; i < 8; i++)
#pragma unroll
                for (int j = 0; j < 8; j++)
                    acc[i][j] += a[i] * bq[j];
        }
        __syncthreads();
    }

    // epilogue: + b_ih, write to g_xproj (m*4096 + n)
    float bias[8];
#pragma unroll
    for (int j = 0; j < 8; j++) bias[j] = b_ih[n0 + tx * 8 + j];
#pragma unroll
    for (int i = 0; i < 8; i++) {
        const size_t base = (size_t)(m0 + ty * 8 + i) * NG + (n0 + tx * 8);
        float4 o0, o1;
        o0.x = acc[i][0] + bias[0]; o0.y = acc[i][1] + bias[1];
        o0.z = acc[i][2] + bias[2]; o0.w = acc[i][3] + bias[3];
        o1.x = acc[i][4] + bias[4]; o1.y = acc[i][5] + bias[5];
        o1.z = acc[i][6] + bias[6]; o1.w = acc[i][7] + bias[7];
        *(float4*)(&g_xproj[base])     = o0;
        *(float4*)(&g_xproj[base + 4]) = o1;
    }
}

// =====================================================================
// Kernel B: persistent LSTM recurrence.
// 128 CTAs x 256 threads. CTA k owns hidden units [k*8, k*8+8) => 32 gate
// rows of W_hh resident in smem for all 512 steps. Per step: all CTAs read
// full h (double-buffered global), compute their 32x64 gate block, update
// c (registers) and h (global), grid-barrier.
// =====================================================================
__device__ __forceinline__ void grid_barrier(unsigned int nb, unsigned int& gen)
{
    __syncthreads();
    if (threadIdx.x == 0) {
        __threadfence();
        const unsigned int target = gen + 1u;
        const unsigned int cnt = atomicAdd(&g_bar_arrive, 1u) + 1u;
        if (cnt == target * nb) {
            __threadfence();
            atomicExch(&g_bar_gen, target);
        } else {
            while (*((volatile unsigned int*)&g_bar_gen) < target) { __nanosleep(64); }
        }
        __threadfence();
    }
    gen++;
    __syncthreads();
}

__global__ __launch_bounds__(256, 1)
void lstm_kernel(const float* __restrict__ h0, const float* __restrict__ c0,
                 const float* __restrict__ W_hh, const float* __restrict__ b_hh,
                 const float* __restrict__ fc_w, const float* __restrict__ fc_b,
                 float* __restrict__ out, int out_size)
{
    extern __shared__ float smem[];
    float* sw   = smem;                    // [32][1028] W_hh slice (padded)
    float* sh   = smem + 32 * 1028;        // [64][128]  h K-tile (XOR swizzled)
    float* sred = sh + 64 * 128;           // [4][2048]  k-slice partials

    const int tid = threadIdx.x;
    const int cta = blockIdx.x;
    const int j0 = cta * 8;                // first owned hidden unit

    // ---- load W_hh slice into smem: local row r = q*8+u -> global row q*H + j0 + u
    for (int i = tid; i < 32 * 256; i += 256) {
        const int r = i >> 8;              // 0..31
        const int c4 = i & 255;            // float4 column
        const int q = r >> 3, u = r & 7;
        const float4* wr = (const float4*)(W_hh + (size_t)(q * NH + j0 + u) * NH);
        ((float4*)(sw + r * 1028))[c4] = wr[c4];
    }

    // ---- per-thread gate-update pairs: same batch b, units jl0 and jl0+4
    const int b   = tid & 63;
    const int jl0 = tid >> 6;              // 0..3
    const int jl1 = jl0 + 4;               // 4..7

    float creg0 = c0[b * NH + j0 + jl0];
    float creg1 = c0[b * NH + j0 + jl1];
    g_hbuf[0][b * NH + j0 + jl0] = h0[b * NH + j0 + jl0];
    g_hbuf[0][b * NH + j0 + jl1] = h0[b * NH + j0 + jl1];

    float bh0[4], bh1[4];
#pragma unroll
    for (int q = 0; q < 4; q++) {
        bh0[q] = b_hh[q * NH + j0 + jl0];
        bh1[q] = b_hh[q * NH + j0 + jl1];
    }

    // ---- GEMM thread mapping: 4 k-slices x 64 positions; 4 rows x 8 batches per thread
    const int ks  = tid >> 6;              // k-slice 0..3
    const int pos = tid & 63;
    const int rb  = pos >> 3;              // row block (4 rows each)
    const int bb  = pos & 7;               // batch block (8 batches each)

    unsigned int gen = 0;
    grid_barrier(NCTA, gen);               // h0 init visible everywhere

    float hlast0 = 0.0f, hlast1 = 0.0f;

    for (int s = 0; s < NS; s++) {
        const float* hread  = g_hbuf[s & 1];
        float*       hwrite = g_hbuf[(s + 1) & 1];

        // prefetch this step's xproj gate inputs (DRAM latency hidden by GEMM)
        const size_t xbase = ((size_t)s * NB + b) * NG + j0;
        float xg0[4], xg1[4];
#pragma unroll
        for (int q = 0; q < 4; q++) {
            xg0[q] = __ldg(&g_xproj[xbase + q * NH + jl0]);
            xg1[q] = __ldg(&g_xproj[xbase + q * NH + jl1]);
        }

        float acc[4][8];
#pragma unroll
        for (int i = 0; i < 4; i++)
#pragma unroll
            for (int j = 0; j < 8; j++) acc[i][j] = 0.0f;

        for (int kt = 0; kt < 8; kt++) {
            __syncthreads();
            // load h K-tile [64][128] -> swizzled smem (ldcg: bypass stale L1)
#pragma unroll
            for (int i = 0; i < 8; i++) {
                const int g  = tid + 256 * i;      // 0..2047 float4s
                const int gb = g >> 5;             // batch 0..63
                const int gc = g & 31;             // chunk 0..31
                const float4 v = __ldcg((const float4*)(hread + gb * NH + kt * 128 + gc * 4));
                const int cs = gc ^ (gb & 31);
                *(float4*)(sh + gb * 128 + cs * 4) = v;
            }
            __syncthreads();
#pragma unroll
            for (int t = 0; t < 8; t++) {
                const int k4  = ks + t * 4;        // chunk within tile
                const int col = kt * 128 + k4 * 4; // column within 1024
                const float4 w0 = *(const float4*)(sw + (rb * 4 + 0) * 1028 + col);
                const float4 w1 = *(const float4*)(sw + (rb * 4 + 1) * 1028 + col);
                const float4 w2 = *(const float4*)(sw + (rb * 4 + 2) * 1028 + col);
                const float4 w3 = *(const float4*)(sw + (rb * 4 + 3) * 1028 + col);
#pragma unroll
                for (int j = 0; j < 8; j++) {
                    const int hb = bb * 8 + j;
                    const int cs = k4 ^ (hb & 31);
                    const float4 hv = *(const float4*)(sh + hb * 128 + cs * 4);
                    acc[0][j] += w0.x * hv.x; acc[0][j] += w0.y * hv.y;
                    acc[0][j] += w0.z * hv.z; acc[0][j] += w0.w * hv.w;
                    acc[1][j] += w1.x * hv.x; acc[1][j] += w1.y * hv.y;
                    acc[1][j] += w1.z * hv.z; acc[1][j] += w1.w * hv.w;
                    acc[2][j] += w2.x * hv.x; acc[2][j] += w2.y * hv.y;
                    acc[2][j] += w2.z * hv.z; acc[2][j] += w2.w * hv.w;
                    acc[3][j] += w3.x * hv.x; acc[3][j] += w3.y * hv.y;
                    acc[3][j] += w3.z * hv.z; acc[3][j] += w3.w * hv.w;
                }
            }
        }

        // ---- cross-k-slice reduction via smem
#pragma unroll
        for (int i = 0; i < 4; i++)
#pragma unroll
            for (int j = 0; j < 8; j++)
                sred[ks * 2048 + pos * 32 + i * 8 + j] = acc[i][j];
        __syncthreads();

        // ---- gate math + state update (2 (b, unit) pairs per thread)
        {
            float gs[4];
#pragma unroll
            for (int q = 0; q < 4; q++) {
                const int r = q * 8 + jl0;
                const int idx = ((r >> 2) * 8 + (b >> 3)) * 32 + (r & 3) * 8 + (b & 7);
                gs[q] = sred[idx] + sred[2048 + idx] + sred[4096 + idx] + sred[6144 + idx]
                        + xg0[q] + bh0[q];
            }
            const float ig = sigm(gs[0]), fg = sigm(gs[1]);
            const float gg = tanhf(gs[2]), og = sigm(gs[3]);
            creg0 = fg * creg0 + ig * gg;
            hlast0 = og * tanhf(creg0);
            hwrite[b * NH + j0 + jl0] = hlast0;
        }
        {
            float gs[4];
#pragma unroll
            for (int q = 0; q < 4; q++) {
                const int r = q * 8 + jl1;
                const int idx = ((r >> 2) * 8 + (b >> 3)) * 32 + (r & 3) * 8 + (b & 7);
                gs[q] = sred[idx] + sred[2048 + idx] + sred[4096 + idx] + sred[6144 + idx]
                        + xg1[q] + bh1[q];
            }
            const float ig = sigm(gs[0]), fg = sigm(gs[1]);
            const float gg = tanhf(gs[2]), og = sigm(gs[3]);
            creg1 = fg * creg1 + ig * gg;
            hlast1 = og * tanhf(creg1);
            hwrite[b * NH + j0 + jl1] = hlast1;
        }

        grid_barrier(NCTA, gen);
    }

    // ---- outputs: [sig_out(64) | h(64x1024) | c(64x1024)]
    if (out_size >= 64 + NB * NH) {
        out[64 + b * NH + j0 + jl0] = hlast0;
        out[64 + b * NH + j0 + jl1] = hlast1;
    }
    if (out_size >= 64 + 2 * NB * NH) {
        out[64 + NB * NH + b * NH + j0 + jl0] = creg0;
        out[64 + NB * NH + b * NH + j0 + jl1] = creg1;
    }
    if (cta == 0 && tid < 64 && out_size >= 64) {
        const float* hfin = g_hbuf[0];  // NS even -> final h in buffer 0
        float a = fc_b[0];
        for (int k = 0; k < NH; k += 4) {
            const float4 hv = __ldcg((const float4*)(hfin + tid * NH + k));
            const float4 wv = *(const float4*)(fc_w + k);
            a += hv.x * wv.x; a += hv.y * wv.y; a += hv.z * wv.z; a += hv.w * wv.w;
        }
        out[tid] = sigm(a);
    }
}

// =====================================================================
extern "C" void kernel_launch(void* const* d_in, const int* in_sizes, int n_in,
                              void* d_out, int out_size)
{
    const int*   x    = (const int*)d_in[0];
    const float* h0   = (const float*)d_in[1];
    const float* c0   = (const float*)d_in[2];
    const float* emb  = (const float*)d_in[3];
    const float* W_ih = (const float*)d_in[4];
    const float* W_hh = (const float*)d_in[5];
    const float* b_ih = (const float*)d_in[6];
    const float* b_hh = (const float*)d_in[7];
    const float* fc_w = (const float*)d_in[8];
    const float* fc_b = (const float*)d_in[9];
    float* out = (float*)d_out;

    const int lstm_smem = (32 * 1028 + 64 * 128 + 4 * 2048) * (int)sizeof(float); // 197120 B
    cudaFuncSetAttribute(lstm_kernel, cudaFuncAttributeMaxDynamicSharedMemorySize, lstm_smem);

    init_kernel<<<1, 1>>>();                              // reset grid-barrier state
    dim3 grid_x(32, 256);                                 // N-tiles x M-tiles
    xproj_kernel<<<grid_x, 256>>>(x, emb, W_ih, b_ih);    // big parallel GEMM
    lstm_kernel<<<NCTA, 256, lstm_smem>>>(h0, c0, W_hh, b_hh, fc_w, fc_b, out, out_size);
}

// round 9
// speedup vs baseline: 3.3572x; 3.3572x over previous
#include <cuda_runtime.h>
#include <cstdint>
#include <cstddef>

#define NB    64      // batch
#define NS    512     // seq len
#define NE    512     // embed dim
#define NH    1024    // hidden
#define NG    4096    // 4*H
#define NCTA  128     // persistent CTAs (1 per SM)

typedef unsigned long long u64;

// ---------------- scratch (device globals: sanctioned, no allocation) ----------------
__device__ float g_xproj[(size_t)NS * NB * NG];   // 512 MB: [s][b][4H]
__device__ float g_hbuf[2][NB * NH];              // double-buffered h
__device__ unsigned int g_bar_arrive;
__device__ unsigned int g_bar_gen;

__global__ void init_kernel() {
    g_bar_arrive = 0u;
    g_bar_gen = 0u;
}

__device__ __forceinline__ float sigm(float v) { return 1.0f / (1.0f + __expf(-v)); }

// ---- packed fp32x2 helpers (Blackwell dual-rate fp32; ptxas never auto-fuses) ----
__device__ __forceinline__ u64 pk2(float lo, float hi) {
    u64 r; asm("mov.b64 %0, {%1, %2};" : "=l"(r) : "f"(lo), "f"(hi)); return r;
}
__device__ __forceinline__ void upk2(u64 v, float& lo, float& hi) {
    asm("mov.b64 {%0, %1}, %2;" : "=f"(lo), "=f"(hi) : "l"(v));
}
__device__ __forceinline__ u64 ff2(u64 a, u64 b, u64 c) {   // a*b + c, both lanes
    u64 d; asm("fma.rn.f32x2 %0, %1, %2, %3;" : "=l"(d) : "l"(a), "l"(b), "l"(c)); return d;
}

// =====================================================================
// Kernel A: xproj[s][b][g] = sum_e emb[x[b][s]][e] * W_ih[g][e] + b_ih[g]
// GEMM M=32768, N=4096, K=512. BM=BN=128, BK=16, 256 thr, 8x8/thread.
// fp32x2 paired along N (B-cols); smem columns skewed phys(c)=c+4*(c>>5)
// so the 8-float per-thread spacing hits 2-wavefront-optimal banking.
// =====================================================================
#define AST 140   // skewed row stride (floats); max phys = 139

__global__ __launch_bounds__(256, 1)
void xproj_kernel(const int* __restrict__ x,
                  const float* __restrict__ emb,
                  const float* __restrict__ W_ih,
                  const float* __restrict__ b_ih)
{
    __shared__ __align__(16) float As[16 * AST];
    __shared__ __align__(16) float Bs[16 * AST];

    const int tid = threadIdx.x;
    const int nt = blockIdx.x;       // 0..31
    const int mt = blockIdx.y;       // 0..255
    const int m0 = mt * 128;
    const int n0 = nt * 128;

    const int lrow = tid >> 2;       // 0..63
    const int lch  = tid & 3;        // float4 chunk within 16-k slab

    const int mA0 = m0 + lrow;
    const int mA1 = mA0 + 64;
    const int tok0 = x[(mA0 & 63) * NS + (mA0 >> 6)];
    const int tok1 = x[(mA1 & 63) * NS + (mA1 >> 6)];
    const float4* a0p = (const float4*)(emb + (size_t)tok0 * NE);
    const float4* a1p = (const float4*)(emb + (size_t)tok1 * NE);
    const float4* b0p = (const float4*)(W_ih + (size_t)(n0 + lrow) * NE);
    const float4* b1p = (const float4*)(W_ih + (size_t)(n0 + lrow + 64) * NE);

    const int tx = tid & 15;         // n-dir thread coord
    const int ty = tid >> 4;         // m-dir thread coord

    // skewed column positions
    const int pm0 = lrow + ((lrow >> 5) << 2);
    const int pm1 = (lrow + 64) + (((lrow + 64) >> 5) << 2);
    const int pa  = ty * 8 + ((ty >> 2) << 2);
    const int pb  = tx * 8 + ((tx >> 2) << 2);

    u64 acc[8][4];                   // pairs along n: lanes = cols (2jp, 2jp+1)
#pragma unroll
    for (int i = 0; i < 8; i++)
#pragma unroll
        for (int jp = 0; jp < 4; jp++) acc[i][jp] = 0ull;

    float4 av0 = a0p[lch], av1 = a1p[lch], bv0 = b0p[lch], bv1 = b1p[lch];

    for (int kt = 0; kt < 32; kt++) {
        const int kl = lch * 4;
        As[(kl + 0) * AST + pm0] = av0.x; As[(kl + 1) * AST + pm0] = av0.y;
        As[(kl + 2) * AST + pm0] = av0.z; As[(kl + 3) * AST + pm0] = av0.w;
        As[(kl + 0) * AST + pm1] = av1.x; As[(kl + 1) * AST + pm1] = av1.y;
        As[(kl + 2) * AST + pm1] = av1.z; As[(kl + 3) * AST + pm1] = av1.w;
        Bs[(kl + 0) * AST + pm0] = bv0.x; Bs[(kl + 1) * AST + pm0] = bv0.y;
        Bs[(kl + 2) * AST + pm0] = bv0.z; Bs[(kl + 3) * AST + pm0] = bv0.w;
        Bs[(kl + 0) * AST + pm1] = bv1.x; Bs[(kl + 1) * AST + pm1] = bv1.y;
        Bs[(kl + 2) * AST + pm1] = bv1.z; Bs[(kl + 3) * AST + pm1] = bv1.w;
        __syncthreads();

        if (kt < 31) {               // prefetch next slab under compute
            const int kc = (kt + 1) * 4 + lch;
            av0 = a0p[kc]; av1 = a1p[kc]; bv0 = b0p[kc]; bv1 = b1p[kc];
        }

#pragma unroll
        for (int k = 0; k < 16; k++) {
            const float4 aa0 = *(const float4*)&As[k * AST + pa];
            const float4 aa1 = *(const float4*)&As[k * AST + pa + 4];
            const ulonglong2 bq0 = *(const ulonglong2*)&Bs[k * AST + pb];
            const ulonglong2 bq1 = *(const ulonglong2*)&Bs[k * AST + pb + 4];
            const u64 b2[4] = {bq0.x, bq0.y, bq1.x, bq1.y};
            const float a[8] = {aa0.x, aa0.y, aa0.z, aa0.w, aa1.x, aa1.y, aa1.z, aa1.w};
#pragma unroll
            for (int i = 0; i < 8; i++) {
                const u64 ad = pk2(a[i], a[i]);   // alu-pipe mov, hidden under FMA
#pragma unroll
                for (int jp = 0; jp < 4; jp++)
                    acc[i][jp] = ff2(ad, b2[jp], acc[i][jp]);
            }
        }
        __syncthreads();
    }

    // epilogue: + b_ih, streaming store to g_xproj
    float bias[8];
#pragma unroll
    for (int j = 0; j < 8; j++) bias[j] = b_ih[n0 + tx * 8 + j];
#pragma unroll
    for (int i = 0; i < 8; i++) {
        float o[8];
#pragma unroll
        for (int jp = 0; jp < 4; jp++) upk2(acc[i][jp], o[2 * jp], o[2 * jp + 1]);
        const size_t base = (size_t)(m0 + ty * 8 + i) * NG + (n0 + tx * 8);
        float4 o0, o1;
        o0.x = o[0] + bias[0]; o0.y = o[1] + bias[1];
        o0.z = o[2] + bias[2]; o0.w = o[3] + bias[3];
        o1.x = o[4] + bias[4]; o1.y = o[5] + bias[5];
        o1.z = o[6] + bias[6]; o1.w = o[7] + bias[7];
        __stcs((float4*)&g_xproj[base], o0);       // evict-first: 512MB stream
        __stcs((float4*)&g_xproj[base + 4], o1);
    }
}

// =====================================================================
// Kernel B: persistent LSTM recurrence, fp32x2 paired along K.
// 128 CTAs x 256 threads. CTA owns 8 hidden units = 32 gate rows of W_hh
// resident in smem (stride 1028). h tiles double-buffered in smem with
// swizzle cs = gc ^ (gb>>3)  (conflict-free reads AND min-wavefront stores).
// =====================================================================
__device__ __forceinline__ void grid_barrier(unsigned int nb, unsigned int& gen)
{
    __syncthreads();
    if (threadIdx.x == 0) {
        __threadfence();
        const unsigned int target = gen + 1u;
        const unsigned int cnt = atomicAdd(&g_bar_arrive, 1u) + 1u;
        if (cnt == target * nb) {
            atomicExch(&g_bar_gen, target);
        } else {
            while (*((volatile unsigned int*)&g_bar_gen) < target) { __nanosleep(32); }
        }
        __threadfence();
    }
    gen++;
    __syncthreads();
}

__global__ __launch_bounds__(256, 1)
void lstm_kernel(const float* __restrict__ h0, const float* __restrict__ c0,
                 const float* __restrict__ W_hh, const float* __restrict__ b_hh,
                 const float* __restrict__ fc_w, const float* __restrict__ fc_b,
                 float* __restrict__ out, int out_size)
{
    extern __shared__ __align__(16) float smem[];
    float* sw   = smem;                    // [32][1028] W_hh slice     (131584 B)
    float* shb  = smem + 32 * 1028;        // 2 x [64][128] h tiles     ( 65536 B)
    float* sred = shb + 2 * 8192;          // [4][64*33] k-slice partials (33792 B)
                                           // total 230912 B <= 232448

    const int tid = threadIdx.x;
    const int cta = blockIdx.x;
    const int j0 = cta * 8;

    // ---- W_hh slice: local row r holds gate row (r>>3)*NH + j0 + (r&7)
    for (int i = tid; i < 32 * 256; i += 256) {
        const int r = i >> 8;
        const int c4 = i & 255;
        const int q = r >> 3, u = r & 7;
        ((float4*)(sw + r * 1028))[c4] =
            ((const float4*)(W_hh + (size_t)(q * NH + j0 + u) * NH))[c4];
    }

    // ---- gate-update mapping: same batch b, units jl0 and jl0+4
    const int b   = tid & 63;
    const int jl0 = tid >> 6;
    const int jl1 = jl0 + 4;

    float creg0 = c0[b * NH + j0 + jl0];
    float creg1 = c0[b * NH + j0 + jl1];
    g_hbuf[0][b * NH + j0 + jl0] = h0[b * NH + j0 + jl0];
    g_hbuf[0][b * NH + j0 + jl1] = h0[b * NH + j0 + jl1];

    float bh0[4], bh1[4];
#pragma unroll
    for (int q = 0; q < 4; q++) {
        bh0[q] = b_hh[q * NH + j0 + jl0];
        bh1[q] = b_hh[q * NH + j0 + jl1];
    }

    // ---- GEMM mapping: 4 k-slices x 64 positions; rows {rb, rb+8, rb+16, rb+24}
    const int ks  = tid >> 6;
    const int pos = tid & 63;
    const int rb  = pos >> 3;              // unit within the 8 owned
    const int bb  = pos & 7;               // batch block (8 batches)

    unsigned int gen = 0;
    grid_barrier(NCTA, gen);               // h0 visible everywhere

    float hlast0 = 0.0f, hlast1 = 0.0f;

    for (int s = 0; s < NS; s++) {
        const float* hread  = g_hbuf[s & 1];
        float*       hwrite = g_hbuf[(s + 1) & 1];

        // xproj gate inputs for this step (latency hidden under GEMM)
        const size_t xbase = ((size_t)s * NB + b) * NG + j0;
        float xg0[4], xg1[4];
#pragma unroll
        for (int q = 0; q < 4; q++) {
            xg0[q] = __ldcg(&g_xproj[xbase + q * NH + jl0]);
            xg1[q] = __ldcg(&g_xproj[xbase + q * NH + jl1]);
        }

        u64 acc[4][8];                     // pairs: even/odd-k partial sums
#pragma unroll
        for (int i = 0; i < 4; i++)
#pragma unroll
            for (int j = 0; j < 8; j++) acc[i][j] = 0ull;

        // prologue: fetch + store tile 0
        float4 pf[8];
#pragma unroll
        for (int i = 0; i < 8; i++) {
            const int g = tid + (i << 8); const int gb = g >> 5, gc = g & 31;
            pf[i] = __ldcg((const float4*)(hread + gb * NH + (gc << 2)));
        }
#pragma unroll
        for (int i = 0; i < 8; i++) {
            const int g = tid + (i << 8); const int gb = g >> 5, gc = g & 31;
            const int cs = gc ^ (gb >> 3);
            *(float4*)(shb + gb * 128 + (cs << 2)) = pf[i];
        }

#pragma unroll 2
        for (int kt = 0; kt < 8; kt++) {
            __syncthreads();
            const float* scur = shb + ((kt & 1) << 13);
            float*       snxt = shb + (((kt + 1) & 1) << 13);

            if (kt < 7) {                  // prefetch next tile under compute
#pragma unroll
                for (int i = 0; i < 8; i++) {
                    const int g = tid + (i << 8); const int gb = g >> 5, gc = g & 31;
                    pf[i] = __ldcg((const float4*)(hread + gb * NH + ((kt + 1) << 7) + (gc << 2)));
                }
            }

#pragma unroll
            for (int t = 0; t < 8; t++) {
                const int k4   = ks + (t << 2);
                const int wcol = (kt << 7) + (k4 << 2);
                const ulonglong2 w0 = *(const ulonglong2*)(sw + (rb +  0) * 1028 + wcol);
                const ulonglong2 w1 = *(const ulonglong2*)(sw + (rb +  8) * 1028 + wcol);
                const ulonglong2 w2 = *(const ulonglong2*)(sw + (rb + 16) * 1028 + wcol);
                const ulonglong2 w3 = *(const ulonglong2*)(sw + (rb + 24) * 1028 + wcol);
                const int cs = k4 ^ bb;    // conflict-free: bb spans all 8 bank groups
#pragma unroll
                for (int j = 0; j < 8; j++) {
                    const int hb = (bb << 3) + j;
                    const ulonglong2 hv = *(const ulonglong2*)(scur + hb * 128 + (cs << 2));
                    acc[0][j] = ff2(w0.x, hv.x, acc[0][j]);
                    acc[0][j] = ff2(w0.y, hv.y, acc[0][j]);
                    acc[1][j] = ff2(w1.x, hv.x, acc[1][j]);
                    acc[1][j] = ff2(w1.y, hv.y, acc[1][j]);
                    acc[2][j] = ff2(w2.x, hv.x, acc[2][j]);
                    acc[2][j] = ff2(w2.y, hv.y, acc[2][j]);
                    acc[3][j] = ff2(w3.x, hv.x, acc[3][j]);
                    acc[3][j] = ff2(w3.y, hv.y, acc[3][j]);
                }
            }

            if (kt < 7) {                  // commit prefetched tile
#pragma unroll
                for (int i = 0; i < 8; i++) {
                    const int g = tid + (i << 8); const int gb = g >> 5, gc = g & 31;
                    const int cs = gc ^ (gb >> 3);
                    *(float4*)(snxt + gb * 128 + (cs << 2)) = pf[i];
                }
            }
        }

        // ---- fold pairs, cross-k-slice reduction (stride 33: conflict-free)
#pragma unroll
        for (int i = 0; i < 4; i++)
#pragma unroll
            for (int j = 0; j < 8; j++) {
                float lo, hi; upk2(acc[i][j], lo, hi);
                sred[ks * 2112 + pos * 33 + (i << 3) + j] = lo + hi;
            }
        __syncthreads();

        // ---- gate math + state update: partial for (row=8q+jl, batch=b) lives at
        //      pos' = jl*8 + (b>>3), slot q*8 + (b&7)
        {
            float gs[4];
#pragma unroll
            for (int q = 0; q < 4; q++) {
                const int idx = ((jl0 << 3) + (b >> 3)) * 33 + (q << 3) + (b & 7);
                gs[q] = sred[idx] + sred[2112 + idx] + sred[4224 + idx] + sred[6336 + idx]
                        + xg0[q] + bh0[q];
            }
            const float ig = sigm(gs[0]), fg = sigm(gs[1]);
            const float gg = tanhf(gs[2]), og = sigm(gs[3]);
            creg0 = fg * creg0 + ig * gg;
            hlast0 = og * tanhf(creg0);
            hwrite[b * NH + j0 + jl0] = hlast0;
        }
        {
            float gs[4];
#pragma unroll
            for (int q = 0; q < 4; q++) {
                const int idx = ((jl1 << 3) + (b >> 3)) * 33 + (q << 3) + (b & 7);
                gs[q] = sred[idx] + sred[2112 + idx] + sred[4224 + idx] + sred[6336 + idx]
                        + xg1[q] + bh1[q];
            }
            const float ig = sigm(gs[0]), fg = sigm(gs[1]);
            const float gg = tanhf(gs[2]), og = sigm(gs[3]);
            creg1 = fg * creg1 + ig * gg;
            hlast1 = og * tanhf(creg1);
            hwrite[b * NH + j0 + jl1] = hlast1;
        }

        grid_barrier(NCTA, gen);
    }

    // ---- outputs: [sig_out(64) | h(64x1024) | c(64x1024)]
    if (out_size >= 64 + NB * NH) {
        out[64 + b * NH + j0 + jl0] = hlast0;
        out[64 + b * NH + j0 + jl1] = hlast1;
    }
    if (out_size >= 64 + 2 * NB * NH) {
        out[64 + NB * NH + b * NH + j0 + jl0] = creg0;
        out[64 + NB * NH + b * NH + j0 + jl1] = creg1;
    }
    if (cta == 0 && tid < 64 && out_size >= 64) {
        const float* hfin = g_hbuf[0];     // NS even -> final h in buffer 0
        float a = fc_b[0];
        for (int k = 0; k < NH; k += 4) {
            const float4 hv = __ldcg((const float4*)(hfin + tid * NH + k));
            const float4 wv = *(const float4*)(fc_w + k);
            a += hv.x * wv.x; a += hv.y * wv.y; a += hv.z * wv.z; a += hv.w * wv.w;
        }
        out[tid] = sigm(a);
    }
}

// =====================================================================
extern "C" void kernel_launch(void* const* d_in, const int* in_sizes, int n_in,
                              void* d_out, int out_size)
{
    const int*   x    = (const int*)d_in[0];
    const float* h0   = (const float*)d_in[1];
    const float* c0   = (const float*)d_in[2];
    const float* emb  = (const float*)d_in[3];
    const float* W_ih = (const float*)d_in[4];
    const float* W_hh = (const float*)d_in[5];
    const float* b_hh_ = (const float*)d_in[7];
    const float* b_ih = (const float*)d_in[6];
    const float* fc_w = (const float*)d_in[8];
    const float* fc_b = (const float*)d_in[9];
    float* out = (float*)d_out;

    const int lstm_smem = (32 * 1028 + 2 * 8192 + 4 * 2112) * (int)sizeof(float); // 230912 B
    cudaFuncSetAttribute(lstm_kernel, cudaFuncAttributeMaxDynamicSharedMemorySize, lstm_smem);

    init_kernel<<<1, 1>>>();                              // reset grid-barrier state
    dim3 grid_x(32, 256);                                 // N-tiles x M-tiles
    xproj_kernel<<<grid_x, 256>>>(x, emb, W_ih, b_ih);
    lstm_kernel<<<NCTA, 256, lstm_smem>>>(h0, c0, W_hh, b_hh_, fc_w, fc_b, out, out_size);
}